// round 7
// baseline (speedup 1.0000x reference)
#include <cuda_runtime.h>
#include <cuda_bf16.h>
#include <cstdint>

#define BB 2
#define HH 16
#define LL 2048
#define DD 64
#define TOPK 64
#define QT 32            // queries per CTA
#define KC 128           // keys per chunk
#define NCHUNK (LL/KC)   // 16
#define SEGCH 4          // chunks per segment
#define SEGK  (SEGCH*KC) // 512 keys per segment
#define NSEG  (NCHUNK/SEGCH)  // 4
#define NWARP 16
#define NTHREADS 512
#define SSTRIDE 520      // score row stride (floats); 520%32=8 -> conflict-free STS.64

// ---- smem layout (bytes) ----
#define SC_OFF    0
#define SC_BYTES  (QT*SSTRIDE*4)              // 66560
#define KBUF_OFF  SC_BYTES                    // 66560 (128B aligned)
#define KSTAGE    32768                       // khi(16K)+klo(16K)
#define QHI_OFF   (KBUF_OFF + 2*KSTAGE)       // 132096
#define QLO_OFF   (QHI_OFF + QT*128)          // +4096
#define HIST_OFF  (QLO_OFF + QT*128)          // +4096 -> 140288
#define CAND_OFF  (HIST_OFF + NWARP*256*4)    // +16384 -> 156672
#define SMEM_BYTES (CAND_OFF + QT*256*8)      // +65536 -> 222208

// ---- persistent bf16 hi/lo split of K (prep kernel output) ----
#define PREP_N (BB*HH*LL*DD/4)
__device__ __align__(16) uint2 KhiG[PREP_N];   // 8MB
__device__ __align__(16) uint2 KloG[PREP_N];   // 8MB

__device__ __forceinline__ uint32_t swz(uint32_t o) { return o ^ ((o >> 3) & 0x70u); }
__device__ __forceinline__ uint32_t sptr(const void* p) {
    return (uint32_t)__cvta_generic_to_shared(p);
}
__device__ __forceinline__ uint32_t pack_bf16(float a, float b) {
    __nv_bfloat162 t = __floats2bfloat162_rn(a, b);
    return *reinterpret_cast<uint32_t*>(&t);
}
__device__ __forceinline__ void cp_async16(uint32_t dst, const void* src) {
    asm volatile("cp.async.cg.shared.global [%0], [%1], 16;" :: "r"(dst), "l"(src));
}
__device__ __forceinline__ void ldsm_x4(uint32_t a[4], uint32_t addr) {
    asm volatile("ldmatrix.sync.aligned.m8n8.x4.shared.b16 {%0,%1,%2,%3}, [%4];"
                 : "=r"(a[0]), "=r"(a[1]), "=r"(a[2]), "=r"(a[3]) : "r"(addr));
}
__device__ __forceinline__ void mma16816(float c[4], const uint32_t a[4], const uint32_t b[2]) {
    asm volatile("mma.sync.aligned.m16n8k16.row.col.f32.bf16.bf16.f32 "
                 "{%0,%1,%2,%3}, {%4,%5,%6,%7}, {%8,%9}, {%0,%1,%2,%3};"
                 : "+f"(c[0]), "+f"(c[1]), "+f"(c[2]), "+f"(c[3])
                 : "r"(a[0]), "r"(a[1]), "r"(a[2]), "r"(a[3]), "r"(b[0]), "r"(b[1]));
}
__device__ __forceinline__ unsigned ordkey(float f) {
    unsigned u = __float_as_uint(f);
    return (u & 0x80000000u) ? ~u : (u | 0x80000000u);
}

// ---- prep: split K into bf16 hi + residual-lo ----
__global__ __launch_bounds__(256) void prep_k_kernel(const float4* __restrict__ K) {
    int i = blockIdx.x * 256 + threadIdx.x;
    float4 v = K[i];
    __nv_bfloat162 h01 = __floats2bfloat162_rn(v.x, v.y);
    __nv_bfloat162 h23 = __floats2bfloat162_rn(v.z, v.w);
    float l0 = v.x - __bfloat162float(h01.x);
    float l1 = v.y - __bfloat162float(h01.y);
    float l2 = v.z - __bfloat162float(h23.x);
    float l3 = v.w - __bfloat162float(h23.y);
    KhiG[i] = make_uint2(*reinterpret_cast<uint32_t*>(&h01),
                         *reinterpret_cast<uint32_t*>(&h23));
    KloG[i] = make_uint2(pack_bf16(l0, l1), pack_bf16(l2, l3));
}

// warp-level scan over a 256-bin histogram: find digit bucket crossing rank r
__device__ __forceinline__ void hist_scan(const uint32_t* myhist, int lane, int r,
                                          int& bsel, int& rnew) {
    const unsigned FULL = 0xFFFFFFFFu;
    unsigned h[8], s = 0;
    int b0 = lane * 8;
#pragma unroll
    for (int j = 0; j < 8; j++) { h[j] = myhist[b0 + j]; s += h[j]; }
    unsigned t = s;                 // suffix-inclusive scan (high lanes = high digits)
#pragma unroll
    for (int d = 1; d < 32; d <<= 1) {
        unsigned v = __shfl_down_sync(FULL, t, d);
        if (lane + d < 32) t += v;
    }
    unsigned above = t - s;
    bool cross = (above < (unsigned)r) && ((unsigned)r <= t);
    unsigned cmask = __ballot_sync(FULL, cross);
    int src = __ffs(cmask) - 1;
    int bs = 0, rn = 0;
    if (cross) {
        unsigned cum = above;
#pragma unroll
        for (int j = 7; j >= 0; j--) {
            cum += h[j];
            if (cum >= (unsigned)r) { bs = b0 + j; rn = r - (int)(cum - h[j]); break; }
        }
    }
    bsel = __shfl_sync(FULL, bs, src);
    rnew = __shfl_sync(FULL, rn, src);
}

// top-64 of a 512-key score segment (16-bit ordered keys, 2-round histogram);
// emits exactly 64 (val, global_idx) pairs: keys > T16 in index order, then
// the first r2 keys == T16 in index order.
__device__ __forceinline__ void select_seg(const float* srow, uint2* out,
                                           uint32_t* myhist, int lane, int seg)
{
    const unsigned FULL = 0xFFFFFFFFu;
    float v[16]; uint32_t kp[8];
    for (int b = lane; b < 256; b += 32) myhist[b] = 0;
    __syncwarp();
#pragma unroll
    for (int j = 0; j < 16; j += 2) {
        float f0 = srow[j * 32 + lane];
        float f1 = srow[(j + 1) * 32 + lane];
        unsigned u0 = ordkey(f0), u1 = ordkey(f1);
        v[j] = f0; v[j + 1] = f1;
        kp[j >> 1] = (u0 >> 16) | (u1 & 0xFFFF0000u);
        atomicAdd(&myhist[u0 >> 24], 1u);
        atomicAdd(&myhist[u1 >> 24], 1u);
    }
    __syncwarp();
    int b1, r1; hist_scan(myhist, lane, TOPK, b1, r1);
    __syncwarp();
    for (int b = lane; b < 256; b += 32) myhist[b] = 0;
    __syncwarp();
#pragma unroll
    for (int j = 0; j < 16; j++) {
        unsigned k = (j & 1) ? (kp[j >> 1] >> 16) : (kp[j >> 1] & 0xFFFFu);
        if ((int)(k >> 8) == b1) atomicAdd(&myhist[k & 255u], 1u);
    }
    __syncwarp();
    int b0sel, r2; hist_scan(myhist, lane, r1, b0sel, r2);
    const unsigned T16 = ((unsigned)b1 << 8) | (unsigned)b0sel;
    const unsigned lt = (1u << lane) - 1u;

    int cnt = 0;
#pragma unroll
    for (int j = 0; j < 16; j++) {
        unsigned k = (j & 1) ? (kp[j >> 1] >> 16) : (kp[j >> 1] & 0xFFFFu);
        bool gt = (k > T16);
        unsigned mg = __ballot_sync(FULL, gt);
        if (gt) out[cnt + __popc(mg & lt)] =
            make_uint2(__float_as_uint(v[j]), (unsigned)(seg * SEGK + j * 32 + lane));
        cnt += __popc(mg);
    }
    int ecnt = 0;
#pragma unroll
    for (int j = 0; j < 16; j++) {
        unsigned k = (j & 1) ? (kp[j >> 1] >> 16) : (kp[j >> 1] & 0xFFFFu);
        bool eq = (k == T16);
        unsigned me = __ballot_sync(FULL, eq);
        if (eq) {
            int p = ecnt + __popc(me & lt);
            if (p < r2) out[cnt + p] =
                make_uint2(__float_as_uint(v[j]), (unsigned)(seg * SEGK + j * 32 + lane));
        }
        ecnt += __popc(me);
    }
    __syncwarp();
}

// final top-64 over the 256 banked candidates; writes into crow[0..63]
__device__ __forceinline__ void select_fin(uint2* crow, uint32_t* myhist, int lane)
{
    const unsigned FULL = 0xFFFFFFFFu;
    uint2 e[8]; uint32_t kp[4];
    for (int b = lane; b < 256; b += 32) myhist[b] = 0;
    __syncwarp();
#pragma unroll
    for (int j = 0; j < 8; j += 2) {
        e[j]     = crow[j * 32 + lane];
        e[j + 1] = crow[(j + 1) * 32 + lane];
        unsigned u0 = ordkey(__uint_as_float(e[j].x));
        unsigned u1 = ordkey(__uint_as_float(e[j + 1].x));
        kp[j >> 1] = (u0 >> 16) | (u1 & 0xFFFF0000u);
        atomicAdd(&myhist[u0 >> 24], 1u);
        atomicAdd(&myhist[u1 >> 24], 1u);
    }
    __syncwarp();
    int b1, r1; hist_scan(myhist, lane, TOPK, b1, r1);
    __syncwarp();
    for (int b = lane; b < 256; b += 32) myhist[b] = 0;
    __syncwarp();
#pragma unroll
    for (int j = 0; j < 8; j++) {
        unsigned k = (j & 1) ? (kp[j >> 1] >> 16) : (kp[j >> 1] & 0xFFFFu);
        if ((int)(k >> 8) == b1) atomicAdd(&myhist[k & 255u], 1u);
    }
    __syncwarp();
    int b0sel, r2; hist_scan(myhist, lane, r1, b0sel, r2);
    const unsigned T16 = ((unsigned)b1 << 8) | (unsigned)b0sel;
    const unsigned lt = (1u << lane) - 1u;

    int cnt = 0;
#pragma unroll
    for (int j = 0; j < 8; j++) {
        unsigned k = (j & 1) ? (kp[j >> 1] >> 16) : (kp[j >> 1] & 0xFFFFu);
        bool gt = (k > T16);
        unsigned mg = __ballot_sync(FULL, gt);
        if (gt) crow[cnt + __popc(mg & lt)] = e[j];
        cnt += __popc(mg);
    }
    int ecnt = 0;
#pragma unroll
    for (int j = 0; j < 8; j++) {
        unsigned k = (j & 1) ? (kp[j >> 1] >> 16) : (kp[j >> 1] & 0xFFFFu);
        bool eq = (k == T16);
        unsigned me = __ballot_sync(FULL, eq);
        if (eq) {
            int p = ecnt + __popc(me & lt);
            if (p < r2) crow[cnt + p] = e[j];
        }
        ecnt += __popc(me);
    }
    __syncwarp();
}

__global__ __launch_bounds__(NTHREADS, 1)
void topk_attn_kernel(const float* __restrict__ Qg, const float* __restrict__ Vg,
                      float* __restrict__ Og)
{
    extern __shared__ char smem[];
    float*    sc   = (float*)smem;
    char*     qhi  = smem + QHI_OFF;
    char*     qlo  = smem + QLO_OFF;
    uint32_t* hist = (uint32_t*)(smem + HIST_OFF);
    uint2*    cand = (uint2*)(smem + CAND_OFF);
    const uint32_t smem_u32 = sptr(smem);

    const int bh = blockIdx.x >> 6;      // 32 (b,h) pairs
    const int qt = blockIdx.x & 63;      // 64 q-tiles of 32
    const int q0 = qt * QT;
    const float* Qb = Qg + (size_t)bh * LL * DD;
    const float* Vb = Vg + (size_t)bh * LL * DD;

    const int tid  = threadIdx.x;
    const int lane = tid & 31;
    const int warp = tid >> 5;
    const unsigned FULL = 0xFFFFFFFFu;
    uint32_t* myhist = hist + warp * 256;

    // ---- issue K chunk load (bf16 hi/lo, pre-split) via cp.async ----
    const char* khiG = (const char*)KhiG + ((size_t)bh * LL) * 128;
    const char* kloG = (const char*)KloG + ((size_t)bh * LL) * 128;
    auto issue_chunk = [&](int ch) {
        const uint32_t dbase = smem_u32 + KBUF_OFF + (ch & 1) * KSTAGE;
        const size_t gbase = (size_t)ch * KC * 128;
#pragma unroll
        for (int it = 0; it < 4; it++) {
            int fi = tid + it * NTHREADS;       // 0..2047
            int half = fi >> 10;                // 0=hi, 1=lo
            uint32_t off = (uint32_t)(fi & 1023) * 16;
            const char* src = (half ? kloG : khiG) + gbase + off;
            cp_async16(dbase + half * 16384 + swz(off), src);
        }
        asm volatile("cp.async.commit_group;" ::: "memory");
    };

    issue_chunk(0);

    // ---- load Q tile (32 x 64 fp32 -> bf16 hi/lo, swizzled) ----
    {
        int qrow = tid >> 4;          // 0..31
        int dc = (tid & 15) * 4;      // 0..60
        float4 qv4 = *(const float4*)(Qb + (size_t)(q0 + qrow) * DD + dc);
        __nv_bfloat162 h01 = __floats2bfloat162_rn(qv4.x, qv4.y);
        __nv_bfloat162 h23 = __floats2bfloat162_rn(qv4.z, qv4.w);
        float l0 = qv4.x - __bfloat162float(h01.x);
        float l1 = qv4.y - __bfloat162float(h01.y);
        float l2 = qv4.z - __bfloat162float(h23.x);
        float l3 = qv4.w - __bfloat162float(h23.y);
        uint32_t off = swz((uint32_t)(qrow * 128 + dc * 2));
        *(uint2*)(qhi + off) = make_uint2(*reinterpret_cast<uint32_t*>(&h01),
                                          *reinterpret_cast<uint32_t*>(&h23));
        *(uint2*)(qlo + off) = make_uint2(pack_bf16(l0, l1), pack_bf16(l2, l3));
    }
    __syncthreads();

    // ---- preload A fragments (Q): 2 m-tiles x 4 k-steps x (hi,lo) ----
    uint32_t Ah[2][4][4], Al[2][4][4];
#pragma unroll
    for (int mt = 0; mt < 2; mt++) {
        int arow = mt * 16 + (lane & 15);
        int acb = ((lane >> 4) & 1) * 16;
#pragma unroll
        for (int ks = 0; ks < 4; ks++) {
            uint32_t off = swz((uint32_t)(arow * 128 + ks * 32 + acb));
            ldsm_x4(Ah[mt][ks], sptr(qhi + off));
            ldsm_x4(Al[mt][ks], sptr(qlo + off));
        }
    }
    // B (K): warp owns keys [warp*8, warp*8+8); x4 covers 2 k-steps
    const uint32_t brow_off = (uint32_t)((warp * 8 + (lane & 7)) * 128 +
                                         ((lane >> 3) & 3) * 16);
    const uint32_t b0off = swz(brow_off);
    const uint32_t b1off = swz(brow_off + 64);

    // ---- main loop: 16 chunks, segment select every 4 ----
    for (int ch = 0; ch < NCHUNK; ch++) {
        asm volatile("cp.async.wait_group 0;" ::: "memory");
        __syncthreads();
        if (ch + 1 < NCHUNK) issue_chunk(ch + 1);

        const uint32_t khi = smem_u32 + KBUF_OFF + (ch & 1) * KSTAGE;
        const uint32_t klo = khi + 16384;

        uint32_t Bh0[4], Bh1[4], Bl0[4], Bl1[4];
        ldsm_x4(Bh0, khi + b0off);
        ldsm_x4(Bh1, khi + b1off);
        ldsm_x4(Bl0, klo + b0off);
        ldsm_x4(Bl1, klo + b1off);

        float a0[4] = {0.f, 0.f, 0.f, 0.f};
        float a1[4] = {0.f, 0.f, 0.f, 0.f};
        // m-tile 0
        mma16816(a0, Ah[0][0], Bh0);      mma16816(a0, Al[0][0], Bh0);
        mma16816(a0, Ah[0][0], Bl0);
        mma16816(a0, Ah[0][1], Bh0 + 2);  mma16816(a0, Al[0][1], Bh0 + 2);
        mma16816(a0, Ah[0][1], Bl0 + 2);
        mma16816(a0, Ah[0][2], Bh1);      mma16816(a0, Al[0][2], Bh1);
        mma16816(a0, Ah[0][2], Bl1);
        mma16816(a0, Ah[0][3], Bh1 + 2);  mma16816(a0, Al[0][3], Bh1 + 2);
        mma16816(a0, Ah[0][3], Bl1 + 2);
        // m-tile 1
        mma16816(a1, Ah[1][0], Bh0);      mma16816(a1, Al[1][0], Bh0);
        mma16816(a1, Ah[1][0], Bl0);
        mma16816(a1, Ah[1][1], Bh0 + 2);  mma16816(a1, Al[1][1], Bh0 + 2);
        mma16816(a1, Ah[1][1], Bl0 + 2);
        mma16816(a1, Ah[1][2], Bh1);      mma16816(a1, Al[1][2], Bh1);
        mma16816(a1, Ah[1][2], Bl1);
        mma16816(a1, Ah[1][3], Bh1 + 2);  mma16816(a1, Al[1][3], Bh1 + 2);
        mma16816(a1, Ah[1][3], Bl1 + 2);

        // store 32q x 8k tile into the 512-key score window
        {
            int qrow = lane >> 2;
            int kcol = (ch & 3) * KC + warp * 8 + 2 * (lane & 3);
            *(float2*)&sc[qrow * SSTRIDE + kcol]        = make_float2(a0[0], a0[1]);
            *(float2*)&sc[(qrow + 8) * SSTRIDE + kcol]  = make_float2(a0[2], a0[3]);
            *(float2*)&sc[(qrow + 16) * SSTRIDE + kcol] = make_float2(a1[0], a1[1]);
            *(float2*)&sc[(qrow + 24) * SSTRIDE + kcol] = make_float2(a1[2], a1[3]);
        }

        if ((ch & 3) == 3) {
            __syncthreads();
            int seg = ch >> 2;
            select_seg(sc + warp * SSTRIDE,
                       cand + warp * 256 + seg * 64, myhist, lane, seg);
            select_seg(sc + (warp + 16) * SSTRIDE,
                       cand + (warp + 16) * 256 + seg * 64, myhist, lane, seg);
            __syncthreads();
        }
    }

    // ---- final: top-64 over 256 banked candidates, softmax, V gather ----
#pragma unroll 1
    for (int qq = 0; qq < 2; qq++) {
        const int q = warp + qq * 16;
        uint2* crow = cand + q * 256;
        select_fin(crow, myhist, lane);

        uint2 e0 = crow[lane], e1 = crow[lane + 32];
        int   k0 = (int)e0.y,                 k1 = (int)e1.y;
        float v0 = __uint_as_float(e0.x),     v1 = __uint_as_float(e1.x);
        float m = fmaxf(v0, v1);
#pragma unroll
        for (int o = 16; o; o >>= 1) m = fmaxf(m, __shfl_xor_sync(FULL, m, o));
        float ex0 = __expf(v0 - m), ex1 = __expf(v1 - m);
        float s = ex0 + ex1;
#pragma unroll
        for (int o = 16; o; o >>= 1) s += __shfl_xor_sync(FULL, s, o);
        float inv = 1.f / s;
        float w0 = ex0 * inv, w1 = ex1 * inv;

        float o0 = 0.f, o1 = 0.f;
#pragma unroll 8
        for (int i = 0; i < 32; i++) {
            float wa = __shfl_sync(FULL, w0, i); int ka = __shfl_sync(FULL, k0, i);
            float wb = __shfl_sync(FULL, w1, i); int kb = __shfl_sync(FULL, k1, i);
            const float* ra = Vb + (size_t)ka * DD;
            const float* rb = Vb + (size_t)kb * DD;
            o0 += wa * ra[lane];      o1 += wa * ra[lane + 32];
            o0 += wb * rb[lane];      o1 += wb * rb[lane + 32];
        }
        size_t ob = ((size_t)bh * LL + q0 + q) * DD;
        Og[ob + lane]      = o0;
        Og[ob + lane + 32] = o1;
    }
}

extern "C" void kernel_launch(void* const* d_in, const int* in_sizes, int n_in,
                              void* d_out, int out_size)
{
    (void)in_sizes; (void)n_in; (void)out_size;
    const float* Q = (const float*)d_in[0];
    const float* K = (const float*)d_in[1];
    const float* V = (const float*)d_in[2];
    float* O = (float*)d_out;

    prep_k_kernel<<<PREP_N / 256, 256>>>((const float4*)K);

    cudaFuncSetAttribute(topk_attn_kernel,
                         cudaFuncAttributeMaxDynamicSharedMemorySize, SMEM_BYTES);
    dim3 grid(BB * HH * (LL / QT));   // 2048 CTAs
    topk_attn_kernel<<<grid, NTHREADS, SMEM_BYTES>>>(Q, V, O);
}

// round 8
// speedup vs baseline: 1.2618x; 1.2618x over previous
#include <cuda_runtime.h>
#include <cuda_bf16.h>
#include <cstdint>

#define BB 2
#define HH 16
#define LL 2048
#define DD 64
#define TOPK 64
#define QT 16           // queries per CTA
#define KC 128          // keys per chunk
#define NCHUNK (LL/KC)  // 16
#define NWARP 16
#define NTHREADS 512
#define SCORE_STRIDE 2052   // padded fp32 stride

// ---- smem layout (bytes) ----
#define SC_BYTES   (QT*SCORE_STRIDE*4)        // 131328
#define KBUF_OFF   SC_BYTES
#define KSTAGE     32768                      // khi(16K) + klo(16K) per stage
#define QHI_OFF    (KBUF_OFF + 2*KSTAGE)      // +65536
#define QLO_OFF    (QHI_OFF + QT*128)         // +2048
#define HIST_OFF   (QLO_OFF + QT*128)         // +2048
#define SIDX_OFF   (HIST_OFF + NWARP*256*4)   // +16384
#define EIDX_OFF   (SIDX_OFF + NWARP*64*4)    // +4096
#define SMEM_BYTES (EIDX_OFF + NWARP*64*4)    // 225536 total

// ---- persistent bf16 hi/lo split of K (prep kernel output) ----
#define PREP_N (BB*HH*LL*DD/4)   // 1,048,576 float4 groups
__device__ __align__(16) uint2 KhiG[PREP_N];   // 8MB
__device__ __align__(16) uint2 KloG[PREP_N];   // 8MB

__device__ __forceinline__ uint32_t swz(uint32_t o) { return o ^ ((o >> 3) & 0x70u); }
__device__ __forceinline__ uint32_t sptr(const void* p) {
    return (uint32_t)__cvta_generic_to_shared(p);
}
__device__ __forceinline__ uint32_t pack_bf16(float a, float b) {
    __nv_bfloat162 t = __floats2bfloat162_rn(a, b);
    return *reinterpret_cast<uint32_t*>(&t);
}
__device__ __forceinline__ void cp_async16(uint32_t dst, const void* src) {
    asm volatile("cp.async.cg.shared.global [%0], [%1], 16;" :: "r"(dst), "l"(src));
}
__device__ __forceinline__ void ldsm_x4(uint32_t a[4], uint32_t addr) {
    asm volatile("ldmatrix.sync.aligned.m8n8.x4.shared.b16 {%0,%1,%2,%3}, [%4];"
                 : "=r"(a[0]), "=r"(a[1]), "=r"(a[2]), "=r"(a[3]) : "r"(addr));
}
__device__ __forceinline__ void mma16816(float c[4], const uint32_t a[4], const uint32_t b[2]) {
    asm volatile("mma.sync.aligned.m16n8k16.row.col.f32.bf16.bf16.f32 "
                 "{%0,%1,%2,%3}, {%4,%5,%6,%7}, {%8,%9}, {%0,%1,%2,%3};"
                 : "+f"(c[0]), "+f"(c[1]), "+f"(c[2]), "+f"(c[3])
                 : "r"(a[0]), "r"(a[1]), "r"(a[2]), "r"(a[3]), "r"(b[0]), "r"(b[1]));
}
// sign-flip trick: monotonic unsigned ordering of floats
__device__ __forceinline__ unsigned ordkey(float f) {
    unsigned u = __float_as_uint(f);
    return (u & 0x80000000u) ? ~u : (u | 0x80000000u);
}

// ---- prep: split K into bf16 hi + residual-lo, stored bf16-row-major ----
__global__ __launch_bounds__(256) void prep_k_kernel(const float4* __restrict__ K) {
    int i = blockIdx.x * 256 + threadIdx.x;
    float4 v = K[i];
    __nv_bfloat162 h01 = __floats2bfloat162_rn(v.x, v.y);
    __nv_bfloat162 h23 = __floats2bfloat162_rn(v.z, v.w);
    float l0 = v.x - __bfloat162float(h01.x);
    float l1 = v.y - __bfloat162float(h01.y);
    float l2 = v.z - __bfloat162float(h23.x);
    float l3 = v.w - __bfloat162float(h23.y);
    KhiG[i] = make_uint2(*reinterpret_cast<uint32_t*>(&h01),
                         *reinterpret_cast<uint32_t*>(&h23));
    KloG[i] = make_uint2(pack_bf16(l0, l1), pack_bf16(l2, l3));
}

// warp-level scan over a 256-bin histogram: find digit bucket crossing rank r
__device__ __forceinline__ void hist_scan(const uint32_t* myhist, int lane, int r,
                                          int& bsel, int& rnew) {
    const unsigned FULL = 0xFFFFFFFFu;
    unsigned h[8], s = 0;
    int b0 = lane * 8;
#pragma unroll
    for (int j = 0; j < 8; j++) { h[j] = myhist[b0 + j]; s += h[j]; }
    unsigned t = s;                 // suffix-inclusive scan (high lanes = high digits)
#pragma unroll
    for (int d = 1; d < 32; d <<= 1) {
        unsigned v = __shfl_down_sync(FULL, t, d);
        if (lane + d < 32) t += v;
    }
    unsigned above = t - s;
    bool cross = (above < (unsigned)r) && ((unsigned)r <= t);
    unsigned cmask = __ballot_sync(FULL, cross);
    int src = __ffs(cmask) - 1;
    int bs = 0, rn = 0;
    if (cross) {
        unsigned cum = above;
#pragma unroll
        for (int j = 7; j >= 0; j--) {
            cum += h[j];
            if (cum >= (unsigned)r) { bs = b0 + j; rn = r - (int)(cum - h[j]); break; }
        }
    }
    bsel = __shfl_sync(FULL, bs, src);
    rnew = __shfl_sync(FULL, rn, src);
}

__global__ __launch_bounds__(NTHREADS, 1)
void topk_attn_kernel(const float* __restrict__ Qg, const float* __restrict__ Vg,
                      float* __restrict__ Og)
{
    extern __shared__ char smem[];
    float*    sc    = (float*)smem;
    char*     qhi   = smem + QHI_OFF;
    char*     qlo   = smem + QLO_OFF;
    uint32_t* hist  = (uint32_t*)(smem + HIST_OFF);
    uint32_t* sidxA = (uint32_t*)(smem + SIDX_OFF);
    uint32_t* eidxA = (uint32_t*)(smem + EIDX_OFF);
    const uint32_t smem_u32 = sptr(smem);

    const int bh = blockIdx.x >> 7;
    const int qt = blockIdx.x & 127;
    const int q0 = qt * QT;
    const float* Qb = Qg + (size_t)bh * LL * DD;
    const float* Vb = Vg + (size_t)bh * LL * DD;

    const int tid  = threadIdx.x;
    const int lane = tid & 31;
    const int warp = tid >> 5;
    const unsigned FULL = 0xFFFFFFFFu;

    // ---- issue K chunk load (bf16 hi/lo, pre-split) via cp.async ----
    const char* khiG = (const char*)KhiG + ((size_t)bh * LL) * 128;
    const char* kloG = (const char*)KloG + ((size_t)bh * LL) * 128;
    auto issue_chunk = [&](int ch) {
        const uint32_t dbase = smem_u32 + KBUF_OFF + (ch & 1) * KSTAGE;
        const size_t gbase = (size_t)ch * KC * 128;
#pragma unroll
        for (int it = 0; it < 4; it++) {
            int fi = tid + it * NTHREADS;       // 0..2047
            int half = fi >> 10;                // 0=hi, 1=lo
            uint32_t off = (uint32_t)(fi & 1023) * 16;
            const char* src = (half ? kloG : khiG) + gbase + off;
            uint32_t dst = dbase + half * 16384 + swz(off);
            cp_async16(dst, src);
        }
        asm volatile("cp.async.commit_group;" ::: "memory");
    };

    issue_chunk(0);   // start DMA before anything else

    // ---- load Q tile, split bf16 hi/lo into swizzled smem ----
    {
        int qrow = tid >> 5;
        int dc = (tid & 31) * 2;
        float2 qv = *(const float2*)(Qb + (size_t)(q0 + qrow) * DD + dc);
        __nv_bfloat162 hp = __floats2bfloat162_rn(qv.x, qv.y);
        float lx = qv.x - __bfloat162float(hp.x);
        float ly = qv.y - __bfloat162float(hp.y);
        uint32_t off = swz((uint32_t)(qrow * 128 + dc * 2));
        *(uint32_t*)(qhi + off) = *reinterpret_cast<uint32_t*>(&hp);
        *(uint32_t*)(qlo + off) = pack_bf16(lx, ly);
    }
    __syncthreads();

    // ---- preload A fragments (Q, m16k16 per k-step) into registers ----
    uint32_t Ah[4][4], Al[4][4];
    {
        int arow = lane & 15;                  // query row
        int acb = ((lane >> 4) & 1) * 16;      // k-halves
#pragma unroll
        for (int ks = 0; ks < 4; ks++) {
            uint32_t off = swz((uint32_t)(arow * 128 + ks * 32 + acb));
            ldsm_x4(Ah[ks], sptr(qhi + off));
            ldsm_x4(Al[ks], sptr(qlo + off));
        }
    }

    // B (K) addressing: warp owns keys [warp*8, warp*8+8) of each chunk.
    const uint32_t brow_off = (uint32_t)((warp * 8 + (lane & 7)) * 128 +
                                         ((lane >> 3) & 3) * 16);

    // ---- main loop: pipelined K chunks -> 3 independent MMA chains ----
    for (int ch = 0; ch < NCHUNK; ch++) {
        asm volatile("cp.async.wait_group 0;" ::: "memory");
        __syncthreads();
        if (ch + 1 < NCHUNK) issue_chunk(ch + 1);   // overlap next load with MMA

        const uint32_t khi = smem_u32 + KBUF_OFF + (ch & 1) * KSTAGE;
        const uint32_t klo = khi + 16384;
        const uint32_t b0 = swz(brow_off);          // k-steps 0,1
        const uint32_t b1 = swz(brow_off + 64);     // k-steps 2,3

        uint32_t Bh0[4], Bh1[4], Bl0[4], Bl1[4];
        ldsm_x4(Bh0, khi + b0);
        ldsm_x4(Bh1, khi + b1);
        ldsm_x4(Bl0, klo + b0);
        ldsm_x4(Bl1, klo + b1);

        // 3 independent accumulator chains (depth 4 each) for tensor-pipe ILP
        float ahh[4] = {0.f, 0.f, 0.f, 0.f};
        float alh[4] = {0.f, 0.f, 0.f, 0.f};
        float ahl[4] = {0.f, 0.f, 0.f, 0.f};
        mma16816(ahh, Ah[0], Bh0);      mma16816(alh, Al[0], Bh0);
        mma16816(ahl, Ah[0], Bl0);
        mma16816(ahh, Ah[1], Bh0 + 2);  mma16816(alh, Al[1], Bh0 + 2);
        mma16816(ahl, Ah[1], Bl0 + 2);
        mma16816(ahh, Ah[2], Bh1);      mma16816(alh, Al[2], Bh1);
        mma16816(ahl, Ah[2], Bl1);
        mma16816(ahh, Ah[3], Bh1 + 2);  mma16816(alh, Al[3], Bh1 + 2);
        mma16816(ahl, Ah[3], Bl1 + 2);

        // store 16q x 8k accumulator tile (rows = queries, cols = keys)
        {
            int qrow = lane >> 2;
            int kcol = ch * KC + warp * 8 + 2 * (lane & 3);
            float c0 = ahh[0] + alh[0] + ahl[0];
            float c1 = ahh[1] + alh[1] + ahl[1];
            float c2 = ahh[2] + alh[2] + ahl[2];
            float c3 = ahh[3] + alh[3] + ahl[3];
            *(float2*)&sc[qrow * SCORE_STRIDE + kcol]       = make_float2(c0, c1);
            *(float2*)&sc[(qrow + 8) * SCORE_STRIDE + kcol] = make_float2(c2, c3);
        }
    }
    __syncthreads();

    // ---- per-warp top-64 select on 16-bit ordered keys (one warp = one query) ----
    const float* row = sc + warp * SCORE_STRIDE;
    uint32_t* myhist = hist + warp * 256;
    uint32_t* sidx = sidxA + warp * 64;
    uint32_t* eidx = eidxA + warp * 64;

    for (int b = lane; b < 256; b += 32) myhist[b] = 0;
    __syncwarp();

    // pack keys into registers + fused round-1 histogram (digit = key>>8)
    uint32_t kp[32];
#pragma unroll
    for (int j = 0; j < 64; j += 2) {
        unsigned u0 = ordkey(row[j * 32 + lane]);
        unsigned u1 = ordkey(row[(j + 1) * 32 + lane]);
        kp[j >> 1] = (u0 >> 16) | (u1 & 0xFFFF0000u);
        atomicAdd(&myhist[u0 >> 24], 1u);
        atomicAdd(&myhist[u1 >> 24], 1u);
    }
    __syncwarp();

    int b1d, r1;
    hist_scan(myhist, lane, TOPK, b1d, r1);
    __syncwarp();

    for (int b = lane; b < 256; b += 32) myhist[b] = 0;
    __syncwarp();
#pragma unroll
    for (int j = 0; j < 64; j++) {
        unsigned k = (j & 1) ? (kp[j >> 1] >> 16) : (kp[j >> 1] & 0xFFFFu);
        if ((int)(k >> 8) == b1d) atomicAdd(&myhist[k & 255u], 1u);
    }
    __syncwarp();

    int b0sel, r2;
    hist_scan(myhist, lane, r1, b0sel, r2);
    const unsigned T16 = ((unsigned)b1d << 8) | (unsigned)b0sel;

    // collect: all keys > T16, then first r2 keys == T16 in index order
    {
        int cnt = 0, ecnt = 0;
        unsigned lt = (1u << lane) - 1u;
#pragma unroll
        for (int j = 0; j < 64; j++) {
            unsigned k = (j & 1) ? (kp[j >> 1] >> 16) : (kp[j >> 1] & 0xFFFFu);
            int i = j * 32 + lane;
            bool gt = (k > T16), eq = (k == T16);
            unsigned mg = __ballot_sync(FULL, gt);
            unsigned me = __ballot_sync(FULL, eq);
            if (gt) sidx[cnt + __popc(mg & lt)] = (uint32_t)i;
            if (eq) {
                int p = ecnt + __popc(me & lt);
                if (p < TOPK) eidx[p] = (uint32_t)i;
            }
            cnt += __popc(mg); ecnt += __popc(me);
        }
        __syncwarp();
        for (int j = lane; j < r2; j += 32) sidx[cnt + j] = eidx[j];
        __syncwarp();
    }

    // ---- softmax over selected (exact fp32) + V gather epilogue ----
    {
        int k0 = (int)sidx[lane], k1 = (int)sidx[lane + 32];
        float v0 = row[k0], v1 = row[k1];
        float m = fmaxf(v0, v1);
#pragma unroll
        for (int o = 16; o; o >>= 1) m = fmaxf(m, __shfl_xor_sync(FULL, m, o));
        float e0 = __expf(v0 - m), e1 = __expf(v1 - m);
        float s = e0 + e1;
#pragma unroll
        for (int o = 16; o; o >>= 1) s += __shfl_xor_sync(FULL, s, o);
        float inv = 1.f / s;
        float w0 = e0 * inv, w1 = e1 * inv;

        // lane covers output cols [2*lane, 2*lane+1] via float2 loads
        float o0 = 0.f, o1 = 0.f;
#pragma unroll 8
        for (int i = 0; i < 32; i++) {
            float wa = __shfl_sync(FULL, w0, i); int ka = __shfl_sync(FULL, k0, i);
            float wb = __shfl_sync(FULL, w1, i); int kb2 = __shfl_sync(FULL, k1, i);
            float2 va = *(const float2*)(Vb + (size_t)ka * DD + 2 * lane);
            float2 vb = *(const float2*)(Vb + (size_t)kb2 * DD + 2 * lane);
            o0 += wa * va.x + wb * vb.x;
            o1 += wa * va.y + wb * vb.y;
        }
        size_t ob = ((size_t)bh * LL + q0 + warp) * DD;
        *(float2*)(Og + ob + 2 * lane) = make_float2(o0, o1);
    }
}

extern "C" void kernel_launch(void* const* d_in, const int* in_sizes, int n_in,
                              void* d_out, int out_size)
{
    (void)in_sizes; (void)n_in; (void)out_size;
    const float* Q = (const float*)d_in[0];
    const float* K = (const float*)d_in[1];
    const float* V = (const float*)d_in[2];
    float* O = (float*)d_out;

    prep_k_kernel<<<PREP_N / 256, 256>>>((const float4*)K);

    cudaFuncSetAttribute(topk_attn_kernel,
                         cudaFuncAttributeMaxDynamicSharedMemorySize, SMEM_BYTES);
    dim3 grid(BB * HH * (LL / QT));   // 4096 CTAs
    topk_attn_kernel<<<grid, NTHREADS, SMEM_BYTES>>>(Q, V, O);
}